// round 10
// baseline (speedup 1.0000x reference)
#include <cuda_runtime.h>
#include <cuda_fp16.h>
#include <cstdint>
#include <cfloat>

#define NEG_SLOPE 0.2f
#define EPS_F 1e-9f
#define SLOT_BITS 6            // 64 slots per target bucket
#define SLOT (1 << SLOT_BITS)

// ---- fixed device scratch (no allocations allowed) ----
static const int MAX_BN    = 1 << 17;             // >= B*N = 80000
static const long long MAX_SLOTS = (long long)MAX_BN << SLOT_BITS;

__device__ __align__(16) float4 g_es[MAX_BN];     // e_self  [bn]
__device__ __align__(16) float4 g_ea[MAX_BN];     // e_adjc  [bn]
__device__ int g_cnt[MAX_BN];                     // per-target edge counts
__device__ int g_esrc[MAX_SLOTS];                 // bucket: source row sb
__device__ __align__(16) float4 g_e[MAX_SLOTS];   // bucket: edge logits e4
__device__ __align__(8)  uint2  g_xh[(size_t)MAX_BN * 32]; // X in fp16, 256B rows

// ---------------------------------------------------------------------------
// Kernel 1: per-node attention logits, 2 node rows per warp (MLP=2).
// Zeroes g_cnt and emits the fp16 copy of X.
// ---------------------------------------------------------------------------
__global__ void __launch_bounds__(256)
node_logits_kernel(const float* __restrict__ X,
                   const float* __restrict__ As,
                   const float* __restrict__ Aa,
                   int BN)
{
    int gtid = blockIdx.x * blockDim.x + threadIdx.x;
    if (gtid < BN) g_cnt[gtid] = 0;

    int warp = gtid >> 5;
    int lane = threadIdx.x & 31;
    int n0 = warp * 2;
    int n1 = n0 + 1;
    if (n0 >= BN) return;

    float4 x0 = ((const float4*)X)[(size_t)n0 * 32 + lane];
    float4 x1 = (n1 < BN) ? ((const float4*)X)[(size_t)n1 * 32 + lane]
                          : make_float4(0.f, 0.f, 0.f, 0.f);

    {   // fp16 copy (lane l holds halves 4l..4l+3 of its row)
        __half2 lo = __floats2half2_rn(x0.x, x0.y);
        __half2 hi = __floats2half2_rn(x0.z, x0.w);
        uint2 p;
        p.x = *reinterpret_cast<unsigned*>(&lo);
        p.y = *reinterpret_cast<unsigned*>(&hi);
        g_xh[(size_t)n0 * 32 + lane] = p;
    }
    if (n1 < BN) {
        __half2 lo = __floats2half2_rn(x1.x, x1.y);
        __half2 hi = __floats2half2_rn(x1.z, x1.w);
        uint2 p;
        p.x = *reinterpret_cast<unsigned*>(&lo);
        p.y = *reinterpret_cast<unsigned*>(&hi);
        g_xh[(size_t)n1 * 32 + lane] = p;
    }

    int h = lane >> 3, c = lane & 7;
    float4 as = ((const float4*)As)[h * 8 + c];
    float4 aa = ((const float4*)Aa)[h * 8 + c];

    float ds0 = x0.x*as.x + x0.y*as.y + x0.z*as.z + x0.w*as.w;
    float da0 = x0.x*aa.x + x0.y*aa.y + x0.z*aa.z + x0.w*aa.w;
    float ds1 = x1.x*as.x + x1.y*as.y + x1.z*as.z + x1.w*as.w;
    float da1 = x1.x*aa.x + x1.y*aa.y + x1.z*aa.z + x1.w*aa.w;
    #pragma unroll
    for (int off = 4; off >= 1; off >>= 1) {
        ds0 += __shfl_xor_sync(0xffffffffu, ds0, off);
        da0 += __shfl_xor_sync(0xffffffffu, da0, off);
        ds1 += __shfl_xor_sync(0xffffffffu, ds1, off);
        da1 += __shfl_xor_sync(0xffffffffu, da1, off);
    }
    int srcl = (lane & 3) * 8;
    float vs0 = __shfl_sync(0xffffffffu, ds0, srcl);
    float va0 = __shfl_sync(0xffffffffu, da0, srcl);
    float vs1 = __shfl_sync(0xffffffffu, ds1, srcl);
    float va1 = __shfl_sync(0xffffffffu, da1, srcl);
    if (lane < 4) {
        ((float*)&g_es[n0])[lane] = vs0;
        ((float*)&g_ea[n0])[lane] = va0;
    } else if (lane < 8 && n1 < BN) {
        ((float*)&g_es[n1])[lane - 4] = vs1;
        ((float*)&g_ea[n1])[lane - 4] = va1;
    }
}

// ---------------------------------------------------------------------------
// Kernel 2: bucket build, 4 CONTIGUOUS edges per thread, int4 index loads.
// ---------------------------------------------------------------------------
__device__ __forceinline__ void build_store(int tb, int sb)
{
    float4 es = g_es[tb];
    float4 ea = g_ea[sb];
    float4 e;
    e.x = es.x + ea.x; e.y = es.y + ea.y;
    e.z = es.z + ea.z; e.w = es.w + ea.w;
    e.x = (e.x >= 0.f) ? e.x : NEG_SLOPE * e.x;
    e.y = (e.y >= 0.f) ? e.y : NEG_SLOPE * e.y;
    e.z = (e.z >= 0.f) ? e.z : NEG_SLOPE * e.z;
    e.w = (e.w >= 0.f) ? e.w : NEG_SLOPE * e.w;
    int pos = atomicAdd(&g_cnt[tb], 1);
    if (pos < SLOT) {
        long long idx = ((long long)tb << SLOT_BITS) + pos;
        g_esrc[idx] = sb;
        g_e[idx]    = e;
    }
}

__global__ void __launch_bounds__(256)
edge_build_kernel(const int* __restrict__ tgt,
                  const int* __restrict__ src,
                  const int* __restrict__ nptr,
                  int BN, int BE)
{
    int base = (blockIdx.x * blockDim.x + threadIdx.x) * 4;
    if (base >= BE) return;
    int N = *nptr;
    int B = BN / N;
    int E = BE / B;

    if (base + 3 < BE && (base / E) == ((base + 3) / E)) {
        int off = (base / E) * N;
        int4 t4 = *(const int4*)(tgt + base);
        int4 s4 = *(const int4*)(src + base);
        build_store(off + t4.x, off + s4.x);
        build_store(off + t4.y, off + s4.y);
        build_store(off + t4.z, off + s4.z);
        build_store(off + t4.w, off + s4.w);
    } else {
        #pragma unroll
        for (int i = 0; i < 4; i++) {
            int be = base + i;
            if (be < BE) {
                int off = (be / E) * N;
                build_store(off + tgt[be], off + src[be]);
            }
        }
    }
}

// ---------------------------------------------------------------------------
// Kernel 3: fused softmax + message passing. Warp-granularity GRID-STRIDE
// over target nodes (load balance: each warp handles ~17 nodes).
// m2 == 1 exactly, so attn = exp(e - m1) / (1 + eps).
// ---------------------------------------------------------------------------
__device__ __forceinline__ void gather_acc(int kmax, int h, int lane,
                                           const int* __restrict__ s_sb,
                                           const float4* __restrict__ s_a,
                                           float4& acc)
{
    int k = 0;
    for (; k + 4 <= kmax; k += 4) {
        int sbk0 = s_sb[k],   sbk1 = s_sb[k+1];
        int sbk2 = s_sb[k+2], sbk3 = s_sb[k+3];
        float a0 = ((const float*)&s_a[k  ])[h];
        float a1 = ((const float*)&s_a[k+1])[h];
        float a2 = ((const float*)&s_a[k+2])[h];
        float a3 = ((const float*)&s_a[k+3])[h];
        uint2 p0 = g_xh[(size_t)sbk0 * 32 + lane];
        uint2 p1 = g_xh[(size_t)sbk1 * 32 + lane];
        uint2 p2 = g_xh[(size_t)sbk2 * 32 + lane];
        uint2 p3 = g_xh[(size_t)sbk3 * 32 + lane];
        float2 lo, hi;
        lo = __half22float2(*reinterpret_cast<__half2*>(&p0.x));
        hi = __half22float2(*reinterpret_cast<__half2*>(&p0.y));
        acc.x += lo.x*a0; acc.y += lo.y*a0; acc.z += hi.x*a0; acc.w += hi.y*a0;
        lo = __half22float2(*reinterpret_cast<__half2*>(&p1.x));
        hi = __half22float2(*reinterpret_cast<__half2*>(&p1.y));
        acc.x += lo.x*a1; acc.y += lo.y*a1; acc.z += hi.x*a1; acc.w += hi.y*a1;
        lo = __half22float2(*reinterpret_cast<__half2*>(&p2.x));
        hi = __half22float2(*reinterpret_cast<__half2*>(&p2.y));
        acc.x += lo.x*a2; acc.y += lo.y*a2; acc.z += hi.x*a2; acc.w += hi.y*a2;
        lo = __half22float2(*reinterpret_cast<__half2*>(&p3.x));
        hi = __half22float2(*reinterpret_cast<__half2*>(&p3.y));
        acc.x += lo.x*a3; acc.y += lo.y*a3; acc.z += hi.x*a3; acc.w += hi.y*a3;
    }
    for (; k < kmax; k++) {
        int   sbk = s_sb[k];
        float ak  = ((const float*)&s_a[k])[h];
        uint2 p = g_xh[(size_t)sbk * 32 + lane];
        float2 lo = __half22float2(*reinterpret_cast<__half2*>(&p.x));
        float2 hi = __half22float2(*reinterpret_cast<__half2*>(&p.y));
        acc.x += lo.x*ak; acc.y += lo.y*ak; acc.z += hi.x*ak; acc.w += hi.y*ak;
    }
}

__global__ void __launch_bounds__(256)
fused_mp_kernel(int BN, int numWarps, float* __restrict__ out)
{
    __shared__ float4 s_a[8][32];
    __shared__ int    s_sb[8][32];

    int gwarp = (blockIdx.x * blockDim.x + threadIdx.x) >> 5;
    int lane  = threadIdx.x & 31;
    int wloc  = threadIdx.x >> 5;

    for (int tb = gwarp; tb < BN; tb += numWarps) {
        int deg = min(g_cnt[tb], SLOT);
        long long base = (long long)tb << SLOT_BITS;

        // ---- load edges unconditionally (bucket array always in-bounds);
        //      mask garbage lanes below ----
        float4 e0 = g_e[base + lane];
        float4 e1 = g_e[base + lane + 32];
        int   sb0 = g_esrc[base + lane];
        int   sb1 = g_esrc[base + lane + 32];
        bool v0 = lane < deg;
        bool v1 = lane + 32 < deg;
        sb0 = v0 ? sb0 : 0;
        sb1 = v1 ? sb1 : 0;

        // ---- per-head segment max (mask invalid lanes) ----
        float t0x = v0 ? e0.x : -FLT_MAX, t0y = v0 ? e0.y : -FLT_MAX;
        float t0z = v0 ? e0.z : -FLT_MAX, t0w = v0 ? e0.w : -FLT_MAX;
        float m0 = fmaxf(t0x, v1 ? e1.x : -FLT_MAX);
        float m1 = fmaxf(t0y, v1 ? e1.y : -FLT_MAX);
        float m2 = fmaxf(t0z, v1 ? e1.z : -FLT_MAX);
        float m3 = fmaxf(t0w, v1 ? e1.w : -FLT_MAX);
        #pragma unroll
        for (int off = 16; off >= 1; off >>= 1) {
            m0 = fmaxf(m0, __shfl_xor_sync(0xffffffffu, m0, off));
            m1 = fmaxf(m1, __shfl_xor_sync(0xffffffffu, m1, off));
            m2 = fmaxf(m2, __shfl_xor_sync(0xffffffffu, m2, off));
            m3 = fmaxf(m3, __shfl_xor_sync(0xffffffffu, m3, off));
        }

        int h = lane >> 3;
        float4 acc = make_float4(0.f, 0.f, 0.f, 0.f);

        // ---- chunk 0 ----
        {
            float4 a = make_float4(0.f, 0.f, 0.f, 0.f);
            if (v0) {
                a.x = __expf(e0.x - m0);
                a.y = __expf(e0.y - m1);
                a.z = __expf(e0.z - m2);
                a.w = __expf(e0.w - m3);
            }
            s_sb[wloc][lane] = sb0;
            s_a[wloc][lane]  = a;
            __syncwarp();
            gather_acc(min(32, deg), h, lane, s_sb[wloc], s_a[wloc], acc);
            __syncwarp();
        }
        // ---- chunk 1 ----
        if (deg > 32) {
            float4 a = make_float4(0.f, 0.f, 0.f, 0.f);
            if (v1) {
                a.x = __expf(e1.x - m0);
                a.y = __expf(e1.y - m1);
                a.z = __expf(e1.z - m2);
                a.w = __expf(e1.w - m3);
            }
            s_sb[wloc][lane] = sb1;
            s_a[wloc][lane]  = a;
            __syncwarp();
            gather_acc(deg - 32, h, lane, s_sb[wloc], s_a[wloc], acc);
            __syncwarp();
        }

        float sc = 1.f / (1.f + EPS_F);
        acc.x *= sc; acc.y *= sc; acc.z *= sc; acc.w *= sc;
        ((float4*)out)[(size_t)tb * 32 + lane] = acc;
    }
}

// ---------------------------------------------------------------------------
extern "C" void kernel_launch(void* const* d_in, const int* in_sizes, int n_in,
                              void* d_out, int out_size)
{
    const float* X    = (const float*)d_in[0];
    const float* As   = (const float*)d_in[1];
    const float* Aa   = (const float*)d_in[2];
    // d_in[3] = degree (unused by reference)
    const int*   tgt  = (const int*)d_in[4];
    const int*   src  = (const int*)d_in[5];
    const int*   nptr = (const int*)d_in[6];

    int hf  = in_sizes[1];            // H*F = 128
    int BN  = in_sizes[0] / hf;       // B*N
    int BE  = in_sizes[4];            // B*E

    {   // node logits (2 rows/warp) + g_cnt zero + fp16 X copy
        long long total = (long long)BN * 16;   // BN/2 warps
        int blocks = (int)((total + 255) / 256);
        node_logits_kernel<<<blocks, 256>>>(X, As, Aa, BN);
    }
    {   // bucket build (4 contiguous edges per thread)
        int quads  = (BE + 3) >> 2;
        int blocks = (quads + 255) / 256;
        edge_build_kernel<<<blocks, 256>>>(tgt, src, nptr, BN, BE);
    }
    {   // fused softmax + message passing, grid-stride warps
        int blocks   = 592;                       // 4 blocks/SM on 148 SMs
        int numWarps = blocks * (256 / 32);       // 4736 warps
        fused_mp_kernel<<<blocks, 256>>>(BN, numWarps, (float*)d_out);
    }
}

// round 11
// speedup vs baseline: 1.0983x; 1.0983x over previous
#include <cuda_runtime.h>
#include <cuda_fp16.h>
#include <cstdint>
#include <cfloat>

#define NEG_SLOPE 0.2f
#define EPS_F 1e-9f
#define SLOT_BITS 6            // 64 slots per target bucket
#define SLOT (1 << SLOT_BITS)

// ---- fixed device scratch (no allocations allowed) ----
static const int MAX_BN    = 1 << 17;             // >= B*N = 80000
static const long long MAX_SLOTS = (long long)MAX_BN << SLOT_BITS;

__device__ __align__(16) float4 g_es[MAX_BN];     // e_self  [bn]
__device__ __align__(16) float4 g_ea[MAX_BN];     // e_adjc  [bn]
__device__ int g_cnt[MAX_BN];                     // per-target edge counts
__device__ int g_esrc[MAX_SLOTS];                 // bucket: source row sb
__device__ __align__(16) float4 g_e[MAX_SLOTS];   // bucket: edge logits e4
__device__ __align__(8)  uint2  g_xh[(size_t)MAX_BN * 32]; // X in fp16, 256B rows

// ---------------------------------------------------------------------------
// Kernel 1: per-node attention logits, 2 node rows per warp (MLP=2).
// Zeroes g_cnt and emits the fp16 copy of X.
// ---------------------------------------------------------------------------
__global__ void __launch_bounds__(256)
node_logits_kernel(const float* __restrict__ X,
                   const float* __restrict__ As,
                   const float* __restrict__ Aa,
                   int BN)
{
    int gtid = blockIdx.x * blockDim.x + threadIdx.x;
    if (gtid < BN) g_cnt[gtid] = 0;

    int warp = gtid >> 5;
    int lane = threadIdx.x & 31;
    int n0 = warp * 2;
    int n1 = n0 + 1;
    if (n0 >= BN) return;

    float4 x0 = ((const float4*)X)[(size_t)n0 * 32 + lane];
    float4 x1 = (n1 < BN) ? ((const float4*)X)[(size_t)n1 * 32 + lane]
                          : make_float4(0.f, 0.f, 0.f, 0.f);

    {   // fp16 copy (lane l holds halves 4l..4l+3 of its row)
        __half2 lo = __floats2half2_rn(x0.x, x0.y);
        __half2 hi = __floats2half2_rn(x0.z, x0.w);
        uint2 p;
        p.x = *reinterpret_cast<unsigned*>(&lo);
        p.y = *reinterpret_cast<unsigned*>(&hi);
        g_xh[(size_t)n0 * 32 + lane] = p;
    }
    if (n1 < BN) {
        __half2 lo = __floats2half2_rn(x1.x, x1.y);
        __half2 hi = __floats2half2_rn(x1.z, x1.w);
        uint2 p;
        p.x = *reinterpret_cast<unsigned*>(&lo);
        p.y = *reinterpret_cast<unsigned*>(&hi);
        g_xh[(size_t)n1 * 32 + lane] = p;
    }

    int h = lane >> 3, c = lane & 7;
    float4 as = ((const float4*)As)[h * 8 + c];
    float4 aa = ((const float4*)Aa)[h * 8 + c];

    float ds0 = x0.x*as.x + x0.y*as.y + x0.z*as.z + x0.w*as.w;
    float da0 = x0.x*aa.x + x0.y*aa.y + x0.z*aa.z + x0.w*aa.w;
    float ds1 = x1.x*as.x + x1.y*as.y + x1.z*as.z + x1.w*as.w;
    float da1 = x1.x*aa.x + x1.y*aa.y + x1.z*aa.z + x1.w*aa.w;
    #pragma unroll
    for (int off = 4; off >= 1; off >>= 1) {
        ds0 += __shfl_xor_sync(0xffffffffu, ds0, off);
        da0 += __shfl_xor_sync(0xffffffffu, da0, off);
        ds1 += __shfl_xor_sync(0xffffffffu, ds1, off);
        da1 += __shfl_xor_sync(0xffffffffu, da1, off);
    }
    int srcl = (lane & 3) * 8;
    float vs0 = __shfl_sync(0xffffffffu, ds0, srcl);
    float va0 = __shfl_sync(0xffffffffu, da0, srcl);
    float vs1 = __shfl_sync(0xffffffffu, ds1, srcl);
    float va1 = __shfl_sync(0xffffffffu, da1, srcl);
    if (lane < 4) {
        ((float*)&g_es[n0])[lane] = vs0;
        ((float*)&g_ea[n0])[lane] = va0;
    } else if (lane < 8 && n1 < BN) {
        ((float*)&g_es[n1])[lane - 4] = vs1;
        ((float*)&g_ea[n1])[lane - 4] = va1;
    }
}

// ---------------------------------------------------------------------------
// Kernel 2: bucket build, 4 CONTIGUOUS edges per thread, int4 index loads.
// ---------------------------------------------------------------------------
__device__ __forceinline__ void build_store(int tb, int sb)
{
    float4 es = g_es[tb];
    float4 ea = g_ea[sb];
    float4 e;
    e.x = es.x + ea.x; e.y = es.y + ea.y;
    e.z = es.z + ea.z; e.w = es.w + ea.w;
    e.x = (e.x >= 0.f) ? e.x : NEG_SLOPE * e.x;
    e.y = (e.y >= 0.f) ? e.y : NEG_SLOPE * e.y;
    e.z = (e.z >= 0.f) ? e.z : NEG_SLOPE * e.z;
    e.w = (e.w >= 0.f) ? e.w : NEG_SLOPE * e.w;
    int pos = atomicAdd(&g_cnt[tb], 1);
    if (pos < SLOT) {
        long long idx = ((long long)tb << SLOT_BITS) + pos;
        g_esrc[idx] = sb;
        g_e[idx]    = e;
    }
}

__global__ void __launch_bounds__(256)
edge_build_kernel(const int* __restrict__ tgt,
                  const int* __restrict__ src,
                  const int* __restrict__ nptr,
                  int BN, int BE)
{
    int base = (blockIdx.x * blockDim.x + threadIdx.x) * 4;
    if (base >= BE) return;
    int N = *nptr;
    int B = BN / N;
    int E = BE / B;

    if (base + 3 < BE && (base / E) == ((base + 3) / E)) {
        int off = (base / E) * N;
        int4 t4 = *(const int4*)(tgt + base);
        int4 s4 = *(const int4*)(src + base);
        build_store(off + t4.x, off + s4.x);
        build_store(off + t4.y, off + s4.y);
        build_store(off + t4.z, off + s4.z);
        build_store(off + t4.w, off + s4.w);
    } else {
        #pragma unroll
        for (int i = 0; i < 4; i++) {
            int be = base + i;
            if (be < BE) {
                int off = (be / E) * N;
                build_store(off + tgt[be], off + src[be]);
            }
        }
    }
}

// ---------------------------------------------------------------------------
// Kernel 3: fused softmax + message passing. One warp per target node.
// m2 == 1 exactly, so attn = exp(e - m1) / (1 + eps).
// R8 structure; gather loop unrolled x8 for MLP.
// ---------------------------------------------------------------------------
__device__ __forceinline__ void fma_edge(uint2 p, float a, float4& acc)
{
    float2 lo = __half22float2(*reinterpret_cast<__half2*>(&p.x));
    float2 hi = __half22float2(*reinterpret_cast<__half2*>(&p.y));
    acc.x += lo.x * a; acc.y += lo.y * a;
    acc.z += hi.x * a; acc.w += hi.y * a;
}

__device__ __forceinline__ void gather_acc(int kmax, int h, int lane,
                                           const int* __restrict__ s_sb,
                                           const float4* __restrict__ s_a,
                                           float4& acc)
{
    int k = 0;
    for (; k + 8 <= kmax; k += 8) {
        uint2 p0 = g_xh[(size_t)s_sb[k  ] * 32 + lane];
        uint2 p1 = g_xh[(size_t)s_sb[k+1] * 32 + lane];
        uint2 p2 = g_xh[(size_t)s_sb[k+2] * 32 + lane];
        uint2 p3 = g_xh[(size_t)s_sb[k+3] * 32 + lane];
        uint2 p4 = g_xh[(size_t)s_sb[k+4] * 32 + lane];
        uint2 p5 = g_xh[(size_t)s_sb[k+5] * 32 + lane];
        uint2 p6 = g_xh[(size_t)s_sb[k+6] * 32 + lane];
        uint2 p7 = g_xh[(size_t)s_sb[k+7] * 32 + lane];
        fma_edge(p0, ((const float*)&s_a[k  ])[h], acc);
        fma_edge(p1, ((const float*)&s_a[k+1])[h], acc);
        fma_edge(p2, ((const float*)&s_a[k+2])[h], acc);
        fma_edge(p3, ((const float*)&s_a[k+3])[h], acc);
        fma_edge(p4, ((const float*)&s_a[k+4])[h], acc);
        fma_edge(p5, ((const float*)&s_a[k+5])[h], acc);
        fma_edge(p6, ((const float*)&s_a[k+6])[h], acc);
        fma_edge(p7, ((const float*)&s_a[k+7])[h], acc);
    }
    if (k + 4 <= kmax) {
        uint2 p0 = g_xh[(size_t)s_sb[k  ] * 32 + lane];
        uint2 p1 = g_xh[(size_t)s_sb[k+1] * 32 + lane];
        uint2 p2 = g_xh[(size_t)s_sb[k+2] * 32 + lane];
        uint2 p3 = g_xh[(size_t)s_sb[k+3] * 32 + lane];
        fma_edge(p0, ((const float*)&s_a[k  ])[h], acc);
        fma_edge(p1, ((const float*)&s_a[k+1])[h], acc);
        fma_edge(p2, ((const float*)&s_a[k+2])[h], acc);
        fma_edge(p3, ((const float*)&s_a[k+3])[h], acc);
        k += 4;
    }
    for (; k < kmax; k++) {
        uint2 p = g_xh[(size_t)s_sb[k] * 32 + lane];
        fma_edge(p, ((const float*)&s_a[k])[h], acc);
    }
}

__global__ void __launch_bounds__(256)
fused_mp_kernel(int BN, float* __restrict__ out)
{
    __shared__ float4 s_a[8][32];
    __shared__ int    s_sb[8][32];

    int gtid = blockIdx.x * blockDim.x + threadIdx.x;
    int tb   = gtid >> 5;
    int lane = threadIdx.x & 31;
    int wloc = threadIdx.x >> 5;
    if (tb >= BN) return;

    int deg = min(g_cnt[tb], SLOT);
    long long base = (long long)tb << SLOT_BITS;

    // ---- load edges once into registers (<=2 chunks, conditional) ----
    float4 e0 = make_float4(-FLT_MAX, -FLT_MAX, -FLT_MAX, -FLT_MAX);
    float4 e1 = e0;
    int sb0 = 0, sb1 = 0;
    if (lane < deg) {
        e0  = g_e[base + lane];
        sb0 = g_esrc[base + lane];
    }
    if (lane + 32 < deg) {
        e1  = g_e[base + lane + 32];
        sb1 = g_esrc[base + lane + 32];
    }

    // ---- per-head segment max from registers ----
    float m0 = fmaxf(e0.x, e1.x), m1 = fmaxf(e0.y, e1.y);
    float m2 = fmaxf(e0.z, e1.z), m3 = fmaxf(e0.w, e1.w);
    #pragma unroll
    for (int off = 16; off >= 1; off >>= 1) {
        m0 = fmaxf(m0, __shfl_xor_sync(0xffffffffu, m0, off));
        m1 = fmaxf(m1, __shfl_xor_sync(0xffffffffu, m1, off));
        m2 = fmaxf(m2, __shfl_xor_sync(0xffffffffu, m2, off));
        m3 = fmaxf(m3, __shfl_xor_sync(0xffffffffu, m3, off));
    }

    int h = lane >> 3;
    float4 acc = make_float4(0.f, 0.f, 0.f, 0.f);

    // ---- chunk 0 (straight-line) ----
    {
        float4 a = make_float4(0.f, 0.f, 0.f, 0.f);
        if (lane < deg) {
            a.x = __expf(e0.x - m0);
            a.y = __expf(e0.y - m1);
            a.z = __expf(e0.z - m2);
            a.w = __expf(e0.w - m3);
        }
        s_sb[wloc][lane] = sb0;
        s_a[wloc][lane]  = a;
        __syncwarp();
        gather_acc(min(32, deg), h, lane, s_sb[wloc], s_a[wloc], acc);
        __syncwarp();
    }
    // ---- chunk 1 ----
    if (deg > 32) {
        float4 a = make_float4(0.f, 0.f, 0.f, 0.f);
        if (lane + 32 < deg) {
            a.x = __expf(e1.x - m0);
            a.y = __expf(e1.y - m1);
            a.z = __expf(e1.z - m2);
            a.w = __expf(e1.w - m3);
        }
        s_sb[wloc][lane] = sb1;
        s_a[wloc][lane]  = a;
        __syncwarp();
        gather_acc(deg - 32, h, lane, s_sb[wloc], s_a[wloc], acc);
        __syncwarp();
    }

    float sc = 1.f / (1.f + EPS_F);
    acc.x *= sc; acc.y *= sc; acc.z *= sc; acc.w *= sc;
    ((float4*)out)[(size_t)tb * 32 + lane] = acc;
}

// ---------------------------------------------------------------------------
extern "C" void kernel_launch(void* const* d_in, const int* in_sizes, int n_in,
                              void* d_out, int out_size)
{
    const float* X    = (const float*)d_in[0];
    const float* As   = (const float*)d_in[1];
    const float* Aa   = (const float*)d_in[2];
    // d_in[3] = degree (unused by reference)
    const int*   tgt  = (const int*)d_in[4];
    const int*   src  = (const int*)d_in[5];
    const int*   nptr = (const int*)d_in[6];

    int hf  = in_sizes[1];            // H*F = 128
    int BN  = in_sizes[0] / hf;       // B*N
    int BE  = in_sizes[4];            // B*E

    {   // node logits (2 rows/warp) + g_cnt zero + fp16 X copy
        long long total = (long long)BN * 16;   // BN/2 warps
        int blocks = (int)((total + 255) / 256);
        node_logits_kernel<<<blocks, 256>>>(X, As, Aa, BN);
    }
    {   // bucket build (4 contiguous edges per thread)
        int quads  = (BE + 3) >> 2;
        int blocks = (quads + 255) / 256;
        edge_build_kernel<<<blocks, 256>>>(tgt, src, nptr, BN, BE);
    }
    {   // fused softmax + message passing
        long long total = (long long)BN * 32;
        int blocks = (int)((total + 255) / 256);
        fused_mp_kernel<<<blocks, 256>>>(BN, (float*)d_out);
    }
}